// round 1
// baseline (speedup 1.0000x reference)
#include <cuda_runtime.h>
#include <math.h>

#define Bb 2
#define Nn 1000
#define KNN 8
#define FEAT 672
#define DPAIR 128

// -------- scratch (device globals; no allocation) --------
__device__ float d_sq[Bb * Nn];
__device__ int   d_knn[Bb * Nn * KNN];
__device__ float d_feat[Bb * Nn * FEAT];    // x1 | x2 | x3 packed at cols 0,32,160
__device__ float d_sf[Bb * Nn * DPAIR];
__device__ float d_g[Bb * DPAIR];
__device__ float d_hi[Bb * Nn * DPAIR];
__device__ float d_hj[Bb * Nn * DPAIR];
__device__ float d_hg[Bb * DPAIR];

// -------- squared norms: one warp per row --------
__global__ void sq_kernel(const float* __restrict__ x, int ld, int off, int C) {
    int row  = blockIdx.x * 4 + (threadIdx.x >> 5);
    int lane = threadIdx.x & 31;
    if (row >= Bb * Nn) return;
    const float* xr = x + (size_t)row * ld + off;
    float s = 0.f;
    for (int c = lane; c < C; c += 32) { float v = xr[c]; s += v * v; }
    #pragma unroll
    for (int o = 16; o > 0; o >>= 1) s += __shfl_down_sync(0xffffffffu, s, o);
    if (lane == 0) d_sq[row] = s;
}

// -------- kNN: one CTA per (b,i); 8 sequential argmins, tie -> lower index --------
template <int C>
__global__ __launch_bounds__(256) void knn_kernel(const float* __restrict__ x, int ld, int off) {
    __shared__ float sd2[Nn];
    __shared__ float sxi[C];
    __shared__ float rv[256];
    __shared__ int   ri[256];
    int row = blockIdx.x;             // b*Nn + i
    int b   = row / Nn;
    int t   = threadIdx.x;
    const float* xb = x + (size_t)b * Nn * ld + off;
    if (t < C) sxi[t] = x[(size_t)row * ld + off + t];
    __syncthreads();
    float sqi = d_sq[row];
    for (int j = t; j < Nn; j += 256) {
        const float* xj = xb + (size_t)j * ld;
        float dot = 0.f;
        if (C % 4 == 0) {
            const float4* xj4 = (const float4*)xj;
            #pragma unroll
            for (int c4 = 0; c4 < C / 4; c4++) {
                float4 v = xj4[c4];
                dot += sxi[4*c4+0]*v.x + sxi[4*c4+1]*v.y + sxi[4*c4+2]*v.z + sxi[4*c4+3]*v.w;
            }
        } else {
            #pragma unroll
            for (int c = 0; c < C; c++) dot += sxi[c] * xj[c];
        }
        sd2[j] = sqi + d_sq[b * Nn + j] - 2.f * dot;
    }
    __syncthreads();
    for (int k = 0; k < KNN; k++) {
        float bv = 3.4e38f; int bi = Nn;
        for (int j = t; j < Nn; j += 256) {
            float v = sd2[j];
            if (v < bv) { bv = v; bi = j; }   // ascending j -> lowest index kept on ties
        }
        rv[t] = bv; ri[t] = bi;
        __syncthreads();
        for (int s = 128; s > 0; s >>= 1) {
            if (t < s) {
                float ov = rv[t + s]; int oi = ri[t + s];
                if (ov < rv[t] || (ov == rv[t] && oi < ri[t])) { rv[t] = ov; ri[t] = oi; }
            }
            __syncthreads();
        }
        if (t == 0) { d_knn[row * KNN + k] = ri[0]; sd2[ri[0]] = 3.4e38f; }
        __syncthreads();
    }
}

// -------- EdgeConv: one CTA per (b,i); message MLP + max over 8 neighbors --------
template <int CIN, int H, int COUT>
__global__ __launch_bounds__(256) void edgeconv_kernel(
    const float* __restrict__ x, int ld, int off, int off_out,
    const float* __restrict__ w1, const float* __restrict__ b1,
    const float* __restrict__ w2, const float* __restrict__ b2)
{
    __shared__ float se[KNN][2 * CIN];
    __shared__ float sh[KNN][H];
    __shared__ float sxi[CIN];
    __shared__ int   sidx[KNN];
    int row = blockIdx.x;
    int b   = row / Nn;
    int t   = threadIdx.x;
    if (t < CIN) sxi[t] = x[(size_t)row * ld + off + t];
    if (t < KNN) sidx[t] = d_knn[row * KNN + t];
    __syncthreads();
    for (int idx = t; idx < KNN * CIN; idx += 256) {
        int k = idx / CIN, c = idx % CIN;
        float xj = x[((size_t)b * Nn + sidx[k]) * ld + off + c];
        se[k][c]       = sxi[c];
        se[k][CIN + c] = xj - sxi[c];
    }
    __syncthreads();
    // layer 1: u per thread, stream w1 column once, 8 neighbors in registers
    for (int u = t; u < H; u += 256) {
        float acc[KNN];
        float bb = b1[u];
        #pragma unroll
        for (int k = 0; k < KNN; k++) acc[k] = bb;
        for (int c = 0; c < 2 * CIN; c++) {
            float w = w1[c * H + u];
            #pragma unroll
            for (int k = 0; k < KNN; k++) acc[k] += se[k][c] * w;
        }
        #pragma unroll
        for (int k = 0; k < KNN; k++) sh[k][u] = acc[k] > 0.f ? acc[k] : 0.f;
    }
    __syncthreads();
    // layer 2 + max over neighbors
    for (int o = t; o < COUT; o += 256) {
        float acc[KNN];
        #pragma unroll
        for (int k = 0; k < KNN; k++) acc[k] = 0.f;
        for (int u = 0; u < H; u++) {
            float w = w2[u * COUT + o];
            #pragma unroll
            for (int k = 0; k < KNN; k++) acc[k] += sh[k][u] * w;
        }
        float bb = b2[o];
        float mx = acc[0] + bb;
        #pragma unroll
        for (int k = 1; k < KNN; k++) { float v = acc[k] + bb; mx = v > mx ? v : mx; }
        d_feat[(size_t)row * FEAT + off_out + o] = mx;
    }
}

// -------- sf = MLP(672->256 relu ->128) on concat features --------
__global__ __launch_bounds__(256) void sfmlp_kernel(
    const float* __restrict__ w1, const float* __restrict__ b1,
    const float* __restrict__ w2, const float* __restrict__ b2)
{
    __shared__ float sx[FEAT];
    __shared__ float sh[256];
    int row = blockIdx.x;
    int t   = threadIdx.x;
    for (int c = t; c < FEAT; c += 256) sx[c] = d_feat[(size_t)row * FEAT + c];
    __syncthreads();
    {
        float acc = b1[t];
        for (int c = 0; c < FEAT; c++) acc += sx[c] * w1[c * 256 + t];
        sh[t] = acc > 0.f ? acc : 0.f;
    }
    __syncthreads();
    if (t < 128) {
        float acc = b2[t];
        for (int u = 0; u < 256; u++) acc += sh[u] * w2[u * 128 + t];
        d_sf[(size_t)row * 128 + t] = acc;
    }
}

// -------- global max pool over N --------
__global__ void gmax_kernel() {
    int b = blockIdx.x, o = threadIdx.x;  // 128 threads
    float m = -3.4e38f;
    const float* p = d_sf + (size_t)b * Nn * 128 + o;
    for (int n = 0; n < Nn; n++) m = fmaxf(m, p[n * 128]);
    d_g[b * 128 + o] = m;
}

// -------- hi = sf@W[:128], hj = sf@W[128:256] (one CTA per row, 256 threads) ----
__global__ __launch_bounds__(256) void hij_kernel(const float* __restrict__ ecw1) {
    __shared__ float s[128];
    int row = blockIdx.x;
    int t   = threadIdx.x;
    if (t < 128) s[t] = d_sf[(size_t)row * 128 + t];
    __syncthreads();
    int o = t & 127;
    const float* w = ecw1 + (t < 128 ? 0 : 128 * 128);
    float acc = 0.f;
    for (int d = 0; d < 128; d++) acc += s[d] * w[d * 128 + o];
    if (t < 128) d_hi[(size_t)row * 128 + o] = acc;
    else         d_hj[(size_t)row * 128 + o] = acc;
}

// -------- hg = g@W[256:] + b1 --------
__global__ void hg_kernel(const float* __restrict__ ecw1, const float* __restrict__ ecb1) {
    int t = threadIdx.x;  // 256
    int b = t >> 7, o = t & 127;
    float acc = ecb1[o];
    for (int d = 0; d < 128; d++) acc += d_g[b * 128 + d] * ecw1[(256 + d) * 128 + o];
    d_hg[b * 128 + o] = acc;
}

// -------- pair scorer over triu pairs, 32x32 tiles --------
#define TILE 32
#define PADC 132   // pad -> conflict-free float4 LDS
__global__ __launch_bounds__(256) void pair_kernel(
    const float* __restrict__ ecw2, const float* __restrict__ ecb2,
    float* __restrict__ out, int write_logits)
{
    __shared__ __align__(16) float shi[TILE][PADC];
    __shared__ __align__(16) float shj[TILE][PADC];
    __shared__ __align__(16) float shg[128];
    __shared__ __align__(16) float sw2[128];
    int jt = blockIdx.x, it = blockIdx.y, b = blockIdx.z;
    if (jt < it) return;
    int t  = threadIdx.x;
    int i0 = it * TILE, j0 = jt * TILE;
    if (t < 128) { shg[t] = d_hg[b * 128 + t]; sw2[t] = ecw2[t]; }
    __syncthreads();
    for (int idx = t; idx < TILE * 128; idx += 256) {
        int r = idx >> 7, u = idx & 127;
        int gi = i0 + r, gj = j0 + r;
        shi[r][u] = (gi < Nn) ? d_hi[((size_t)b * Nn + gi) * 128 + u] + shg[u] : 0.f;
        shj[r][u] = (gj < Nn) ? d_hj[((size_t)b * Nn + gj) * 128 + u] : 0.f;
    }
    __syncthreads();
    float bias = ecb2[0];
    const long P = (long)Nn * (Nn - 1) / 2;
    #pragma unroll
    for (int p = 0; p < 4; p++) {
        int pid = t + p * 256;
        int ii = pid >> 5, jj = pid & 31;   // ii constant per warp -> broadcast
        int i = i0 + ii, j = j0 + jj;
        if (i < Nn && j < Nn && i < j) {
            const float4* vi = (const float4*)shi[ii];
            const float4* vj = (const float4*)shj[jj];
            const float4* vw = (const float4*)sw2;
            float acc = 0.f;
            #pragma unroll
            for (int q = 0; q < 32; q++) {
                float4 a = vi[q], bq = vj[q], w = vw[q];
                float s;
                s = a.x + bq.x; if (s > 0.f) acc += s * w.x;
                s = a.y + bq.y; if (s > 0.f) acc += s * w.y;
                s = a.z + bq.z; if (s > 0.f) acc += s * w.z;
                s = a.w + bq.w; if (s > 0.f) acc += s * w.w;
            }
            float logit = acc + bias;
            long pidx = (long)b * P + (long)i * (2 * Nn - i - 1) / 2 + (j - i - 1);
            out[pidx] = 1.f / (1.f + expf(-logit));
            if (write_logits) out[(long)Bb * P + pidx] = logit;
        }
    }
}

extern "C" void kernel_launch(void* const* d_in, const int* in_sizes, int n_in,
                              void* d_out, int out_size) {
    const float* pos  = (const float*)d_in[0];
    const float* c1w1 = (const float*)d_in[1];
    const float* c1b1 = (const float*)d_in[2];
    const float* c1w2 = (const float*)d_in[3];
    const float* c1b2 = (const float*)d_in[4];
    const float* c2w1 = (const float*)d_in[5];
    const float* c2b1 = (const float*)d_in[6];
    const float* c2w2 = (const float*)d_in[7];
    const float* c2b2 = (const float*)d_in[8];
    const float* c3w1 = (const float*)d_in[9];
    const float* c3b1 = (const float*)d_in[10];
    const float* c3w2 = (const float*)d_in[11];
    const float* c3b2 = (const float*)d_in[12];
    const float* smw1 = (const float*)d_in[13];
    const float* smb1 = (const float*)d_in[14];
    const float* smw2 = (const float*)d_in[15];
    const float* smb2 = (const float*)d_in[16];
    const float* ecw1 = (const float*)d_in[17];
    const float* ecb1 = (const float*)d_in[18];
    const float* ecw2 = (const float*)d_in[19];
    const float* ecb2 = (const float*)d_in[20];
    float* out = (float*)d_out;

    const long P = (long)Nn * (Nn - 1) / 2;
    int write_logits = ((long)out_size >= 2L * Bb * P) ? 1 : 0;

    float* feat = nullptr;
    cudaGetSymbolAddress((void**)&feat, d_feat);

    const int ROWS = Bb * Nn;

    // stage 1: kNN on pos (C=3), EdgeConv 6->16->32  -> feat[:,0:32]
    sq_kernel<<<(ROWS + 3) / 4, 128>>>(pos, 3, 0, 3);
    knn_kernel<3><<<ROWS, 256>>>(pos, 3, 0);
    edgeconv_kernel<3, 16, 32><<<ROWS, 256>>>(pos, 3, 0, 0, c1w1, c1b1, c1w2, c1b2);

    // stage 2: kNN on x1 (C=32), EdgeConv 64->64->128 -> feat[:,32:160]
    sq_kernel<<<(ROWS + 3) / 4, 128>>>(feat, FEAT, 0, 32);
    knn_kernel<32><<<ROWS, 256>>>(feat, FEAT, 0);
    edgeconv_kernel<32, 64, 128><<<ROWS, 256>>>(feat, FEAT, 0, 32, c2w1, c2b1, c2w2, c2b2);

    // stage 3: kNN on x2 (C=128), EdgeConv 256->256->512 -> feat[:,160:672]
    sq_kernel<<<(ROWS + 3) / 4, 128>>>(feat, FEAT, 32, 128);
    knn_kernel<128><<<ROWS, 256>>>(feat, FEAT, 32);
    edgeconv_kernel<128, 256, 512><<<ROWS, 256>>>(feat, FEAT, 32, 160, c3w1, c3b1, c3w2, c3b2);

    // sf MLP, global max, pair projections
    sfmlp_kernel<<<ROWS, 256>>>(smw1, smb1, smw2, smb2);
    gmax_kernel<<<Bb, 128>>>();
    hij_kernel<<<ROWS, 256>>>(ecw1);
    hg_kernel<<<1, 256>>>(ecw1, ecb1);

    // pair scorer
    dim3 pg((Nn + TILE - 1) / TILE, (Nn + TILE - 1) / TILE, Bb);
    pair_kernel<<<pg, 256>>>(ecw2, ecb2, out, write_logits);
}

// round 5
// speedup vs baseline: 1.4508x; 1.4508x over previous
#include <cuda_runtime.h>
#include <math.h>

#define Bb 2
#define Nn 1000
#define KNN 8
#define FEAT 672
#define DPAIR 128

// ---------------- scratch (device globals; no allocation) ----------------
__device__ int   d_knn[Bb * Nn * KNN];
__device__ float d_feat[Bb * Nn * FEAT];    // x1 | x2 | x3 packed at cols 0,32,160
__device__ float d_sf[Bb * Nn * DPAIR];
__device__ float d_gp[Bb * 8 * DPAIR];
__device__ float d_g[Bb * DPAIR];
__device__ float d_hi[Bb * Nn * DPAIR];
__device__ float d_hj[Bb * Nn * DPAIR];
__device__ float d_hg[Bb * DPAIR];

// ---------------- f32x2 packed helpers ----------------
__device__ __forceinline__ unsigned long long pack2(float v) {
    unsigned long long r;
    asm("mov.b64 %0, {%1, %1};" : "=l"(r) : "f"(v));
    return r;
}
__device__ __forceinline__ unsigned long long packab(float a, float b) {
    unsigned long long r;
    asm("mov.b64 %0, {%1, %2};" : "=l"(r) : "f"(a), "f"(b));
    return r;
}
#define FFMA2(acc, a, b) asm("fma.rn.f32x2 %0, %1, %2, %0;" : "+l"(acc) : "l"(a), "l"(b))
__device__ __forceinline__ void unpk(unsigned long long v, float& lo, float& hi) {
    asm("mov.b64 {%0, %1}, %2;" : "=f"(lo), "=f"(hi) : "l"(v));
}
__device__ __forceinline__ float hsum2(unsigned long long v) {
    float lo, hi; unpk(v, lo, hi); return lo + hi;
}

// ---------------- kNN batched: 8 points per CTA ----------------
template <int C>
__global__ __launch_bounds__(256) void knn_b(const float* __restrict__ x, int ld, int off) {
    __shared__ float sd2[8][Nn];
    __shared__ float sxi[8][C];
    int t  = threadIdx.x;
    int p0 = blockIdx.x * 8;          // global rows p0..p0+7 (same batch: 1000%8==0)
    int b  = p0 / Nn;
    for (int idx = t; idx < 8 * C; idx += 256)
        sxi[idx / C][idx % C] = x[(size_t)(p0 + idx / C) * ld + off + (idx % C)];
    __syncthreads();
    const float* xb = x + (size_t)b * Nn * ld + off;
    for (int j = t; j < Nn; j += 256) {
        if (C % 4 == 0) {
            const float4* xp = (const float4*)(xb + (size_t)j * ld);
            unsigned long long acc[8], nrm = 0ull;
            #pragma unroll
            for (int r = 0; r < 8; r++) acc[r] = 0ull;
            #pragma unroll
            for (int c4 = 0; c4 < C / 4; c4++) {
                float4 v = xp[c4];
                unsigned long long v01 = packab(v.x, v.y);
                unsigned long long v23 = packab(v.z, v.w);
                FFMA2(nrm, v01, v01);
                FFMA2(nrm, v23, v23);
                #pragma unroll
                for (int r = 0; r < 8; r++) {
                    const unsigned long long* s = (const unsigned long long*)(sxi[r]);
                    FFMA2(acc[r], v01, s[2 * c4]);
                    FFMA2(acc[r], v23, s[2 * c4 + 1]);
                }
            }
            float sqj = hsum2(nrm);
            #pragma unroll
            for (int r = 0; r < 8; r++)
                sd2[r][j] = fmaf(-2.f, hsum2(acc[r]), sqj);   // sq_i dropped: constant per row
        } else {
            const float* xj = xb + (size_t)j * ld;
            float v0 = xj[0], v1 = xj[1], v2 = xj[2];
            float sqj = v0 * v0 + v1 * v1 + v2 * v2;
            #pragma unroll
            for (int r = 0; r < 8; r++) {
                float dot = sxi[r][0] * v0 + sxi[r][1] * v1 + sxi[r][2] * v2;
                sd2[r][j] = fmaf(-2.f, dot, sqj);
            }
        }
    }
    __syncthreads();
    // selection: warp w handles row w; 8 sequential argmins, tie -> lower index
    int w = t >> 5, lane = t & 31;
    float* row = sd2[w];
    for (int k = 0; k < KNN; k++) {
        float bv = 3.4e38f; int bi = Nn;
        for (int j = lane; j < Nn; j += 32) {
            float v = row[j];
            if (v < bv) { bv = v; bi = j; }
        }
        #pragma unroll
        for (int o = 16; o > 0; o >>= 1) {
            float ov = __shfl_down_sync(0xffffffffu, bv, o);
            int   oi = __shfl_down_sync(0xffffffffu, bi, o);
            if (ov < bv || (ov == bv && oi < bi)) { bv = ov; bi = oi; }
        }
        bi = __shfl_sync(0xffffffffu, bi, 0);
        if (lane == 0) { d_knn[(p0 + w) * KNN + k] = bi; row[bi] = 3.4e38f; }
        __syncwarp();
    }
}

// ---------------- generic f32x2 GEMM tile (M rows in shared, W streamed) -----
// At: shared [KK][MP] (transposed: At[c][r]); Wg: global row-major [*, ldw].
// Thread (tx,ty): rows r0=ty*TM, cols {col0 + tx*2 + p*64 + (0,1)} for p<NC/64.
template <int KK, int NC, int TM, int MP>
__device__ __forceinline__ void gemm_f2(
    const float* __restrict__ At, const float* __restrict__ Wg, int ldw, int col0,
    float* __restrict__ Wt, unsigned long long (&acc)[TM][4], int tx, int ty, int t)
{
    constexpr int P2 = NC / 64;
    for (int kb = 0; kb < KK; kb += 32) {
        for (int idx = t; idx < 32 * (NC / 4); idx += 256) {
            int c  = idx / (NC / 4);
            int u4 = idx - c * (NC / 4);
            ((float4*)Wt)[idx] = *(const float4*)(Wg + (size_t)(kb + c) * ldw + col0 + u4 * 4);
        }
        __syncthreads();
        #pragma unroll 4
        for (int c = 0; c < 32; c++) {
            const float* arow = At + (kb + c) * MP + ty * TM;
            unsigned long long ep[TM];
            if (TM == 8) {
                float4 a0 = *(const float4*)(arow);
                float4 a1 = *(const float4*)(arow + 4);
                ep[0] = pack2(a0.x); ep[1] = pack2(a0.y); ep[2] = pack2(a0.z); ep[3] = pack2(a0.w);
                if (TM > 4) {
                    ep[4 % TM] = pack2(a1.x); ep[5 % TM] = pack2(a1.y);
                    ep[6 % TM] = pack2(a1.z); ep[7 % TM] = pack2(a1.w);
                }
            } else {
                float2 a = *(const float2*)(arow);
                ep[0] = pack2(a.x); ep[1 % TM] = pack2(a.y);
            }
            const unsigned long long* wrow = (const unsigned long long*)(Wt + c * NC);
            #pragma unroll
            for (int p = 0; p < P2; p++) {
                unsigned long long wv = wrow[tx + p * 32];
                #pragma unroll
                for (int m = 0; m < TM; m++) FFMA2(acc[m][p], ep[m], wv);
            }
        }
        __syncthreads();
    }
}

// ---------------- EdgeConv batched: 8 points (64 edges) per CTA ----------------
template <int CIN, int H, int COUT>
__global__ __launch_bounds__(256) void edgeconv_b(
    const float* __restrict__ x, int ld, int off, int off_out,
    const float* __restrict__ w1, const float* __restrict__ b1,
    const float* __restrict__ w2, const float* __restrict__ b2)
{
    constexpr int MP  = 68;
    constexpr int K1  = 2 * CIN;
    constexpr int NC1 = H;                              // H <= 256
    constexpr int NC2 = (COUT > 256) ? 256 : COUT;
    extern __shared__ float sm[];
    float* sxi = sm;                       // 8*CIN
    float* Et  = sm + 8 * CIN;             // K1*MP
    float* Ht  = Et + K1 * MP;             // H*MP
    float* Wt  = Ht + H * MP;              // 32*max(NC1,NC2)
    __shared__ int sidx[64];
    int t = threadIdx.x, tx = t & 31, ty = t >> 5;
    int p0 = blockIdx.x * 8;
    int b  = p0 / Nn;
    if (t < 64) sidx[t] = d_knn[p0 * KNN + t];
    for (int idx = t; idx < 8 * CIN; idx += 256)
        sxi[idx] = x[(size_t)(p0 + idx / CIN) * ld + off + (idx % CIN)];
    __syncthreads();
    // build E^T[2CIN][64]
    for (int idx = t; idx < 64 * (CIN / 4); idx += 256) {
        int r = idx & 63, c4 = idx >> 6;
        int j = sidx[r];
        float4 v = *(const float4*)(x + ((size_t)b * Nn + j) * ld + off + c4 * 4);
        const float* xi = sxi + (r >> 3) * CIN + c4 * 4;
        float i0 = xi[0], i1 = xi[1], i2 = xi[2], i3 = xi[3];
        Et[(c4 * 4 + 0) * MP + r] = i0;
        Et[(c4 * 4 + 1) * MP + r] = i1;
        Et[(c4 * 4 + 2) * MP + r] = i2;
        Et[(c4 * 4 + 3) * MP + r] = i3;
        Et[(CIN + c4 * 4 + 0) * MP + r] = v.x - i0;
        Et[(CIN + c4 * 4 + 1) * MP + r] = v.y - i1;
        Et[(CIN + c4 * 4 + 2) * MP + r] = v.z - i2;
        Et[(CIN + c4 * 4 + 3) * MP + r] = v.w - i3;
    }
    __syncthreads();
    // GEMM1: H^T = relu(E * W1 + b1)
    unsigned long long acc[8][4];
    #pragma unroll
    for (int m = 0; m < 8; m++)
        #pragma unroll
        for (int p = 0; p < 4; p++) acc[m][p] = 0ull;
    gemm_f2<K1, NC1, 8, MP>(Et, w1, H, 0, Wt, acc, tx, ty, t);
    constexpr int P1 = NC1 / 64;
    #pragma unroll
    for (int p = 0; p < P1; p++) {
        int u0 = tx * 2 + p * 64;
        float bb0 = b1[u0], bb1 = b1[u0 + 1];
        #pragma unroll
        for (int m = 0; m < 8; m++) {
            float lo, hi; unpk(acc[m][p], lo, hi);
            Ht[u0 * MP + ty * 8 + m]       = fmaxf(lo + bb0, 0.f);
            Ht[(u0 + 1) * MP + ty * 8 + m] = fmaxf(hi + bb1, 0.f);
        }
    }
    __syncthreads();
    // GEMM2 + bias + max over the 8 neighbors (rows ty*8..ty*8+7 = point ty)
    for (int col0 = 0; col0 < COUT; col0 += NC2) {
        #pragma unroll
        for (int m = 0; m < 8; m++)
            #pragma unroll
            for (int p = 0; p < 4; p++) acc[m][p] = 0ull;
        gemm_f2<H, NC2, 8, MP>(Ht, w2, COUT, col0, Wt, acc, tx, ty, t);
        constexpr int P2c = NC2 / 64;
        #pragma unroll
        for (int p = 0; p < P2c; p++) {
            int u0 = col0 + tx * 2 + p * 64;
            float bb0 = b2[u0], bb1 = b2[u0 + 1];
            float m0 = -3.4e38f, m1 = -3.4e38f;
            #pragma unroll
            for (int m = 0; m < 8; m++) {
                float lo, hi; unpk(acc[m][p], lo, hi);
                m0 = fmaxf(m0, lo + bb0);
                m1 = fmaxf(m1, hi + bb1);
            }
            float* o = d_feat + (size_t)(p0 + ty) * FEAT + off_out + u0;
            o[0] = m0; o[1] = m1;
        }
    }
}

// ---------------- EdgeConv stage 1 (tiny; per-point CTA) ----------------
template <int CIN, int H, int COUT>
__global__ __launch_bounds__(256) void edgeconv_small(
    const float* __restrict__ x, int ld, int off, int off_out,
    const float* __restrict__ w1, const float* __restrict__ b1,
    const float* __restrict__ w2, const float* __restrict__ b2)
{
    __shared__ float se[KNN][2 * CIN];
    __shared__ float sh[KNN][H];
    __shared__ float sxi[CIN];
    __shared__ int   sidx[KNN];
    int row = blockIdx.x;
    int b   = row / Nn;
    int t   = threadIdx.x;
    if (t < CIN) sxi[t] = x[(size_t)row * ld + off + t];
    if (t < KNN) sidx[t] = d_knn[row * KNN + t];
    __syncthreads();
    for (int idx = t; idx < KNN * CIN; idx += 256) {
        int k = idx / CIN, c = idx % CIN;
        float xj = x[((size_t)b * Nn + sidx[k]) * ld + off + c];
        se[k][c]       = sxi[c];
        se[k][CIN + c] = xj - sxi[c];
    }
    __syncthreads();
    for (int u = t; u < H; u += 256) {
        float a[KNN]; float bb = b1[u];
        #pragma unroll
        for (int k = 0; k < KNN; k++) a[k] = bb;
        for (int c = 0; c < 2 * CIN; c++) {
            float wv = w1[c * H + u];
            #pragma unroll
            for (int k = 0; k < KNN; k++) a[k] += se[k][c] * wv;
        }
        #pragma unroll
        for (int k = 0; k < KNN; k++) sh[k][u] = a[k] > 0.f ? a[k] : 0.f;
    }
    __syncthreads();
    for (int o = t; o < COUT; o += 256) {
        float a[KNN];
        #pragma unroll
        for (int k = 0; k < KNN; k++) a[k] = 0.f;
        for (int u = 0; u < H; u++) {
            float wv = w2[u * COUT + o];
            #pragma unroll
            for (int k = 0; k < KNN; k++) a[k] += sh[k][u] * wv;
        }
        float bb = b2[o];
        float mx = a[0] + bb;
        #pragma unroll
        for (int k = 1; k < KNN; k++) { float v = a[k] + bb; mx = v > mx ? v : mx; }
        d_feat[(size_t)row * FEAT + off_out + o] = mx;
    }
}

// ---------------- sf-MLP batched: 16 points per CTA ----------------
__global__ __launch_bounds__(256) void sfmlp_b(
    const float* __restrict__ w1, const float* __restrict__ b1,
    const float* __restrict__ w2, const float* __restrict__ b2)
{
    constexpr int MP = 20;
    extern __shared__ float sm[];
    float* Xt = sm;                     // 672*20
    float* Ht = Xt + FEAT * MP;         // 256*20
    float* Wt = Ht + 256 * MP;          // 32*256
    int t = threadIdx.x, tx = t & 31, ty = t >> 5;
    int p0 = blockIdx.x * 16;
    for (int idx = t; idx < 16 * (FEAT / 4); idx += 256) {
        int r = idx & 15, c4 = idx >> 4;
        float4 v = *(const float4*)(d_feat + (size_t)(p0 + r) * FEAT + c4 * 4);
        Xt[(c4 * 4 + 0) * MP + r] = v.x;
        Xt[(c4 * 4 + 1) * MP + r] = v.y;
        Xt[(c4 * 4 + 2) * MP + r] = v.z;
        Xt[(c4 * 4 + 3) * MP + r] = v.w;
    }
    __syncthreads();
    unsigned long long acc[2][4];
    #pragma unroll
    for (int m = 0; m < 2; m++)
        #pragma unroll
        for (int p = 0; p < 4; p++) acc[m][p] = 0ull;
    gemm_f2<FEAT, 256, 2, MP>(Xt, w1, 256, 0, Wt, acc, tx, ty, t);
    #pragma unroll
    for (int p = 0; p < 4; p++) {
        int u0 = tx * 2 + p * 64;
        float bb0 = b1[u0], bb1 = b1[u0 + 1];
        #pragma unroll
        for (int m = 0; m < 2; m++) {
            float lo, hi; unpk(acc[m][p], lo, hi);
            Ht[u0 * MP + ty * 2 + m]       = fmaxf(lo + bb0, 0.f);
            Ht[(u0 + 1) * MP + ty * 2 + m] = fmaxf(hi + bb1, 0.f);
        }
    }
    __syncthreads();
    #pragma unroll
    for (int m = 0; m < 2; m++)
        #pragma unroll
        for (int p = 0; p < 4; p++) acc[m][p] = 0ull;
    gemm_f2<256, 128, 2, MP>(Ht, w2, 128, 0, Wt, acc, tx, ty, t);
    #pragma unroll
    for (int p = 0; p < 2; p++) {
        int u0 = tx * 2 + p * 64;
        float bb0 = b2[u0], bb1 = b2[u0 + 1];
        #pragma unroll
        for (int m = 0; m < 2; m++) {
            float lo, hi; unpk(acc[m][p], lo, hi);
            float* o = d_sf + (size_t)(p0 + ty * 2 + m) * 128 + u0;
            o[0] = lo + bb0; o[1] = hi + bb1;
        }
    }
}

// ---------------- global max pool: partial + final ----------------
__global__ void gmax_part() {
    int b = blockIdx.x, s = blockIdx.y, o = threadIdx.x;   // 128 threads
    const float* p = d_sf + ((size_t)b * Nn + s * 125) * 128 + o;
    float m0 = -3.4e38f, m1 = -3.4e38f, m2 = -3.4e38f, m3 = -3.4e38f;
    for (int n = 0; n < 124; n += 4) {
        m0 = fmaxf(m0, p[(n + 0) * 128]);
        m1 = fmaxf(m1, p[(n + 1) * 128]);
        m2 = fmaxf(m2, p[(n + 2) * 128]);
        m3 = fmaxf(m3, p[(n + 3) * 128]);
    }
    m0 = fmaxf(m0, p[124 * 128]);
    d_gp[(b * 8 + s) * 128 + o] = fmaxf(fmaxf(m0, m1), fmaxf(m2, m3));
}
__global__ void gmax_fin() {
    int t = threadIdx.x;        // 256
    int b = t >> 7, o = t & 127;
    float m = -3.4e38f;
    #pragma unroll
    for (int s = 0; s < 8; s++) m = fmaxf(m, d_gp[(b * 8 + s) * 128 + o]);
    d_g[b * 128 + o] = m;
}

// ---------------- hi/hj projection: 8 points per CTA ----------------
__global__ __launch_bounds__(256) void hij_b(const float* __restrict__ ecw1) {
    __shared__ float st[128][10];   // st[d][r], pad 10 keeps u64 pairs aligned
    int t = threadIdx.x;
    int p0 = blockIdx.x * 8;
    for (int idx = t; idx < 8 * 128; idx += 256) {
        int r = idx >> 7, d = idx & 127;
        st[d][r] = d_sf[(size_t)(p0 + r) * 128 + d];
    }
    __syncthreads();
    int col = t & 127, which = t >> 7;
    const float* w = ecw1 + (size_t)which * 128 * 128 + col;
    unsigned long long acc[4] = {0ull, 0ull, 0ull, 0ull};
    for (int d = 0; d < 128; d++) {
        unsigned long long wv = pack2(w[(size_t)d * 128]);
        const unsigned long long* sp = (const unsigned long long*)(&st[d][0]);
        #pragma unroll
        for (int m = 0; m < 4; m++) FFMA2(acc[m], sp[m], wv);
    }
    float* out = which ? d_hj : d_hi;
    #pragma unroll
    for (int m = 0; m < 4; m++) {
        float lo, hi; unpk(acc[m], lo, hi);
        out[(size_t)(p0 + 2 * m) * 128 + col]     = lo;
        out[(size_t)(p0 + 2 * m + 1) * 128 + col] = hi;
    }
}

// ---------------- hg = g @ W[256:] + b1 ----------------
__global__ void hg_kernel(const float* __restrict__ ecw1, const float* __restrict__ ecb1) {
    int t = threadIdx.x;   // 256
    int b = t >> 7, o = t & 127;
    float acc = ecb1[o];
    for (int d = 0; d < 128; d++) acc += d_g[b * 128 + d] * ecw1[(256 + d) * 128 + o];
    d_hg[b * 128 + o] = acc;
}

// ---------------- pair scorer: 32x32 tiles over triu pairs ----------------
#define TILE 32
#define PADC 132
__global__ __launch_bounds__(256) void pair_kernel(
    const float* __restrict__ ecw2, const float* __restrict__ ecb2,
    float* __restrict__ out, int write_logits)
{
    __shared__ __align__(16) float shi[TILE][PADC];
    __shared__ __align__(16) float shj[TILE][PADC];
    __shared__ __align__(16) float shg[128];
    __shared__ __align__(16) float sw2[128];
    int jt = blockIdx.x, it = blockIdx.y, b = blockIdx.z;
    if (jt < it) return;
    int t  = threadIdx.x;
    int i0 = it * TILE, j0 = jt * TILE;
    if (t < 128) { shg[t] = d_hg[b * 128 + t]; sw2[t] = ecw2[t]; }
    __syncthreads();
    for (int idx = t; idx < TILE * 128; idx += 256) {
        int r = idx >> 7, u = idx & 127;
        int gi = i0 + r, gj = j0 + r;
        shi[r][u] = (gi < Nn) ? d_hi[((size_t)b * Nn + gi) * 128 + u] + shg[u] : 0.f;
        shj[r][u] = (gj < Nn) ? d_hj[((size_t)b * Nn + gj) * 128 + u] : 0.f;
    }
    __syncthreads();
    float bias = ecb2[0];
    const long P = (long)Nn * (Nn - 1) / 2;
    #pragma unroll
    for (int p = 0; p < 4; p++) {
        int pid = t + p * 256;
        int ii = pid >> 5, jj = pid & 31;
        int i = i0 + ii, j = j0 + jj;
        if (i < Nn && j < Nn && i < j) {
            const float4* vi = (const float4*)shi[ii];
            const float4* vj = (const float4*)shj[jj];
            const float4* vw = (const float4*)sw2;
            float a0 = 0.f, a1 = 0.f, a2 = 0.f, a3 = 0.f;
            #pragma unroll
            for (int q = 0; q < 32; q++) {
                float4 a = vi[q], bq = vj[q], wv = vw[q];
                a0 += fmaxf(a.x + bq.x, 0.f) * wv.x;
                a1 += fmaxf(a.y + bq.y, 0.f) * wv.y;
                a2 += fmaxf(a.z + bq.z, 0.f) * wv.z;
                a3 += fmaxf(a.w + bq.w, 0.f) * wv.w;
            }
            float logit = (a0 + a1) + (a2 + a3) + bias;
            long pidx = (long)b * P + (long)i * (2 * Nn - i - 1) / 2 + (j - i - 1);
            out[pidx] = 1.f / (1.f + expf(-logit));
            if (write_logits) out[(long)Bb * P + pidx] = logit;
        }
    }
}

extern "C" void kernel_launch(void* const* d_in, const int* in_sizes, int n_in,
                              void* d_out, int out_size) {
    const float* pos  = (const float*)d_in[0];
    const float* c1w1 = (const float*)d_in[1];
    const float* c1b1 = (const float*)d_in[2];
    const float* c1w2 = (const float*)d_in[3];
    const float* c1b2 = (const float*)d_in[4];
    const float* c2w1 = (const float*)d_in[5];
    const float* c2b1 = (const float*)d_in[6];
    const float* c2w2 = (const float*)d_in[7];
    const float* c2b2 = (const float*)d_in[8];
    const float* c3w1 = (const float*)d_in[9];
    const float* c3b1 = (const float*)d_in[10];
    const float* c3w2 = (const float*)d_in[11];
    const float* c3b2 = (const float*)d_in[12];
    const float* smw1 = (const float*)d_in[13];
    const float* smb1 = (const float*)d_in[14];
    const float* smw2 = (const float*)d_in[15];
    const float* smb2 = (const float*)d_in[16];
    const float* ecw1 = (const float*)d_in[17];
    const float* ecb1 = (const float*)d_in[18];
    const float* ecw2 = (const float*)d_in[19];
    const float* ecb2 = (const float*)d_in[20];
    float* out = (float*)d_out;

    const long P = (long)Nn * (Nn - 1) / 2;
    int write_logits = ((long)out_size >= 2L * Bb * P) ? 1 : 0;

    float* feat = nullptr;
    cudaGetSymbolAddress((void**)&feat, d_feat);

    // dynamic smem sizes (floats): sxi + Et + Ht + Wt
    const int SM2 = (8 * 32 + 64 * 68 + 64 * 68 + 32 * 128) * 4;     // 52,224 B
    const int SM3 = (8 * 128 + 256 * 68 + 256 * 68 + 32 * 256) * 4;  // 176,128 B
    const int SMS = (FEAT * 20 + 256 * 20 + 32 * 256) * 4;           // 107,008 B
    cudaFuncSetAttribute(edgeconv_b<32, 64, 128>,  cudaFuncAttributeMaxDynamicSharedMemorySize, SM2);
    cudaFuncSetAttribute(edgeconv_b<128, 256, 512>, cudaFuncAttributeMaxDynamicSharedMemorySize, SM3);
    cudaFuncSetAttribute(sfmlp_b, cudaFuncAttributeMaxDynamicSharedMemorySize, SMS);

    // stage 1: kNN on pos (C=3), EdgeConv 6->16->32 -> feat[:,0:32]
    knn_b<3><<<250, 256>>>(pos, 3, 0);
    edgeconv_small<3, 16, 32><<<Bb * Nn, 256>>>(pos, 3, 0, 0, c1w1, c1b1, c1w2, c1b2);

    // stage 2: kNN on x1 (C=32), EdgeConv 64->64->128 -> feat[:,32:160]
    knn_b<32><<<250, 256>>>(feat, FEAT, 0);
    edgeconv_b<32, 64, 128><<<250, 256, SM2>>>(feat, FEAT, 0, 32, c2w1, c2b1, c2w2, c2b2);

    // stage 3: kNN on x2 (C=128), EdgeConv 256->256->512 -> feat[:,160:672]
    knn_b<128><<<250, 256>>>(feat, FEAT, 32);
    edgeconv_b<128, 256, 512><<<250, 256, SM3>>>(feat, FEAT, 32, 160, c3w1, c3b1, c3w2, c3b2);

    // sf MLP, global max, pair projections
    sfmlp_b<<<125, 256, SMS>>>(smw1, smb1, smw2, smb2);
    dim3 gg(Bb, 8);
    gmax_part<<<gg, 128>>>();
    gmax_fin<<<1, 256>>>();
    hij_b<<<250, 256>>>(ecw1);
    hg_kernel<<<1, 256>>>(ecw1, ecb1);

    // pair scorer
    dim3 pg((Nn + TILE - 1) / TILE, (Nn + TILE - 1) / TILE, Bb);
    pair_kernel<<<pg, 256>>>(ecw2, ecb2, out, write_logits);
}